// round 15
// baseline (speedup 1.0000x reference)
#include <cuda_runtime.h>
#include <cuda_bf16.h>

// CWTConv2D: quantized 3x3 valid conv.
// out[b,i,j,f] = relu( sum_{u,v} round(x[b,i+u,j+v]) * clip(round(kw[f,2-u,2-v]),-1,1)
//                      + round(bias[f]) )
// x (32,512,512) f32, kw (32,3,3) f32, bias (32,) f32 -> out (32,510,510,32) f32 NHWC.
//
// R15 design: STG.128 drain path.
//   lane = (q = lane&7 -> filter group 4q..4q+3, px = lane>>3 -> 16-pixel run)
//   warp = 1 output row x 64 cols; thread = 16 consecutive pixels x 4 filters.
//   Per warp-iter (4 px = 512 B): 3 LDS.32 (broadcast, conflict-free) +
//   36 FFMA + 4 FMNMX + 1 STG.128  -> 4 LSU ops / 512 B (was 8).
//   Halves pressure on the LSU dispatch path that ncu shows pinned at ~67%.

#define BATCH   32
#define HW      512
#define OHW     510
#define NF      32
#define TR      8                    // output rows per block (1 per warp)
#define TC      64                   // output cols per block
#define PXT     16                   // pixels per thread
#define SM_ROWS (TR + 2)             // 10 input rows
#define SM_STRIDE 68                 // 66 needed cols + pad

__global__ __launch_bounds__(256, 4)
void cwtconv2d_kernel(const float* __restrict__ x,
                      const float* __restrict__ kw,
                      const float* __restrict__ bias,
                      float* __restrict__ out)
{
    __shared__ float sx[SM_ROWS * SM_STRIDE];

    const int b   = blockIdx.z;
    const int gr0 = blockIdx.y * TR;
    const int gc0 = blockIdx.x * TC;
    const int tid  = threadIdx.x;
    const int lane = tid & 31;
    const int wrp  = tid >> 5;       // output row within tile
    const int q    = lane & 7;       // filter group: filters 4q..4q+3
    const int px   = lane >> 3;      // pixel-run index: cols [px*16, px*16+16)

    // ---- per-thread weights: 4 filters x 9 taps, quantized + double-flipped ----
    // W[k].{x,y,z,w} = clip(round(kw[4q+{0,1,2,3}, flip(k)]), -1, 1)
    float4 W[9];
    {
        const float* kp = kw + (4 * q) * 9;
        #pragma unroll
        for (int k = 0; k < 9; ++k) {
            W[k].x = fminf(fmaxf(rintf(__ldg(&kp[ 0 + (8 - k)])), -1.0f), 1.0f);
            W[k].y = fminf(fmaxf(rintf(__ldg(&kp[ 9 + (8 - k)])), -1.0f), 1.0f);
            W[k].z = fminf(fmaxf(rintf(__ldg(&kp[18 + (8 - k)])), -1.0f), 1.0f);
            W[k].w = fminf(fmaxf(rintf(__ldg(&kp[27 + (8 - k)])), -1.0f), 1.0f);
        }
    }
    float4 BIA;
    BIA.x = rintf(__ldg(&bias[4 * q + 0]));
    BIA.y = rintf(__ldg(&bias[4 * q + 1]));
    BIA.z = rintf(__ldg(&bias[4 * q + 2]));
    BIA.w = rintf(__ldg(&bias[4 * q + 3]));

    // ---- div-free vectorized fill: 10 rows x 16 float4 tasks (cols 0..63) ----
    // gc0+63 <= 511 always -> only rows need guards. 160 tasks / 256 threads.
    const float* xb = x + (size_t)b * HW * HW;
    for (int t = tid; t < SM_ROWS * 16; t += 256) {
        int r = t >> 4;
        int k = (t & 15) << 2;
        int gr = gr0 + r;
        float4 v = make_float4(0.f, 0.f, 0.f, 0.f);
        if (gr < HW)
            v = *(const float4*)&xb[gr * HW + gc0 + k];
        v.x = rintf(v.x); v.y = rintf(v.y); v.z = rintf(v.z); v.w = rintf(v.w);
        *(float4*)&sx[r * SM_STRIDE + k] = v;
    }
    // tail: tile cols 64..67 (row+col guarded; 40 threads)
    if (tid < SM_ROWS * 4) {
        int r = tid >> 2;
        int c = 64 + (tid & 3);
        int gr = gr0 + r;
        int gc = gc0 + c;
        float v = 0.0f;
        if (gr < HW && gc < HW) v = rintf(xb[gr * HW + gc]);
        sx[r * SM_STRIDE + c] = v;
    }
    __syncthreads();

    const int i = gr0 + wrp;
    if (i >= OHW) return;

    const int c0 = px * PXT;                   // thread's first local col
    const int gcol = gc0 + c0;                 // global col of pixel j=0 (<= 496)

    const float* r0p = &sx[(wrp + 0) * SM_STRIDE + c0];
    const float* r1p = &sx[(wrp + 1) * SM_STRIDE + c0];
    const float* r2p = &sx[(wrp + 2) * SM_STRIDE + c0];

    // per-thread sliding window: cols c, c+1 held for 3 rows
    float a0 = r0p[0], b0 = r0p[1];
    float a1 = r1p[0], b1 = r1p[1];
    float a2 = r2p[0], b2 = r2p[1];

    // store pointer: element (b, i, gcol, 4q); 16B aligned
    float4* op = (float4*)(out + (((size_t)b * OHW + i) * OHW + gcol) * NF + 4 * q);

    #pragma unroll 4
    for (int j = 0; j < PXT; ++j) {
        float n0 = r0p[j + 2];
        float n1 = r1p[j + 2];
        float n2 = r2p[j + 2];

        float4 acc = BIA;
        acc.x = fmaf(a0, W[0].x, acc.x); acc.y = fmaf(a0, W[0].y, acc.y);
        acc.z = fmaf(a0, W[0].z, acc.z); acc.w = fmaf(a0, W[0].w, acc.w);
        acc.x = fmaf(b0, W[1].x, acc.x); acc.y = fmaf(b0, W[1].y, acc.y);
        acc.z = fmaf(b0, W[1].z, acc.z); acc.w = fmaf(b0, W[1].w, acc.w);
        acc.x = fmaf(n0, W[2].x, acc.x); acc.y = fmaf(n0, W[2].y, acc.y);
        acc.z = fmaf(n0, W[2].z, acc.z); acc.w = fmaf(n0, W[2].w, acc.w);

        acc.x = fmaf(a1, W[3].x, acc.x); acc.y = fmaf(a1, W[3].y, acc.y);
        acc.z = fmaf(a1, W[3].z, acc.z); acc.w = fmaf(a1, W[3].w, acc.w);
        acc.x = fmaf(b1, W[4].x, acc.x); acc.y = fmaf(b1, W[4].y, acc.y);
        acc.z = fmaf(b1, W[4].z, acc.z); acc.w = fmaf(b1, W[4].w, acc.w);
        acc.x = fmaf(n1, W[5].x, acc.x); acc.y = fmaf(n1, W[5].y, acc.y);
        acc.z = fmaf(n1, W[5].z, acc.z); acc.w = fmaf(n1, W[5].w, acc.w);

        acc.x = fmaf(a2, W[6].x, acc.x); acc.y = fmaf(a2, W[6].y, acc.y);
        acc.z = fmaf(a2, W[6].z, acc.z); acc.w = fmaf(a2, W[6].w, acc.w);
        acc.x = fmaf(b2, W[7].x, acc.x); acc.y = fmaf(b2, W[7].y, acc.y);
        acc.z = fmaf(b2, W[7].z, acc.z); acc.w = fmaf(b2, W[7].w, acc.w);
        acc.x = fmaf(n2, W[8].x, acc.x); acc.y = fmaf(n2, W[8].y, acc.y);
        acc.z = fmaf(n2, W[8].z, acc.z); acc.w = fmaf(n2, W[8].w, acc.w);

        acc.x = fmaxf(acc.x, 0.0f);
        acc.y = fmaxf(acc.y, 0.0f);
        acc.z = fmaxf(acc.z, 0.0f);
        acc.w = fmaxf(acc.w, 0.0f);

        // column guard only binds in the last column block (gcol+j can reach 511)
        if (gcol + j < OHW)
            __stcs(op, acc);
        op += NF / 4;                 // next pixel: +32 floats

        a0 = b0; b0 = n0;
        a1 = b1; b1 = n1;
        a2 = b2; b2 = n2;
    }
}

extern "C" void kernel_launch(void* const* d_in, const int* in_sizes, int n_in,
                              void* d_out, int out_size)
{
    const float* x    = (const float*)d_in[0];
    const float* kw   = (const float*)d_in[1];
    const float* bias = (const float*)d_in[2];
    float* out = (float*)d_out;

    dim3 grid((OHW + TC - 1) / TC,   // 8
              (OHW + TR - 1) / TR,   // 64
              BATCH);                // 32 -> 16384 blocks
    cwtconv2d_kernel<<<grid, 256>>>(x, kw, bias, out);
}

// round 16
// speedup vs baseline: 1.0130x; 1.0130x over previous
#include <cuda_runtime.h>
#include <cuda_bf16.h>

// CWTConv2D: quantized 3x3 valid conv.
// out[b,i,j,f] = relu( sum_{u,v} round(x[b,i+u,j+v]) * clip(round(kw[f,2-u,2-v]),-1,1)
//                      + round(bias[f]) )
// x (32,512,512) f32, kw (32,3,3) f32, bias (32,) f32 -> out (32,510,510,32) f32 NHWC.
//
// R15 design: STG.128 drain path.
//   lane = (q = lane&7 -> filter group 4q..4q+3, px = lane>>3 -> 16-pixel run)
//   warp = 1 output row x 64 cols; thread = 16 consecutive pixels x 4 filters.
//   Per warp-iter (4 px = 512 B): 3 LDS.32 (broadcast, conflict-free) +
//   36 FFMA + 4 FMNMX + 1 STG.128  -> 4 LSU ops / 512 B (was 8).
//   Halves pressure on the LSU dispatch path that ncu shows pinned at ~67%.

#define BATCH   32
#define HW      512
#define OHW     510
#define NF      32
#define TR      8                    // output rows per block (1 per warp)
#define TC      64                   // output cols per block
#define PXT     16                   // pixels per thread
#define SM_ROWS (TR + 2)             // 10 input rows
#define SM_STRIDE 68                 // 66 needed cols + pad

__global__ __launch_bounds__(256, 4)
void cwtconv2d_kernel(const float* __restrict__ x,
                      const float* __restrict__ kw,
                      const float* __restrict__ bias,
                      float* __restrict__ out)
{
    __shared__ float sx[SM_ROWS * SM_STRIDE];

    const int b   = blockIdx.z;
    const int gr0 = blockIdx.y * TR;
    const int gc0 = blockIdx.x * TC;
    const int tid  = threadIdx.x;
    const int lane = tid & 31;
    const int wrp  = tid >> 5;       // output row within tile
    const int q    = lane & 7;       // filter group: filters 4q..4q+3
    const int px   = lane >> 3;      // pixel-run index: cols [px*16, px*16+16)

    // ---- per-thread weights: 4 filters x 9 taps, quantized + double-flipped ----
    // W[k].{x,y,z,w} = clip(round(kw[4q+{0,1,2,3}, flip(k)]), -1, 1)
    float4 W[9];
    {
        const float* kp = kw + (4 * q) * 9;
        #pragma unroll
        for (int k = 0; k < 9; ++k) {
            W[k].x = fminf(fmaxf(rintf(__ldg(&kp[ 0 + (8 - k)])), -1.0f), 1.0f);
            W[k].y = fminf(fmaxf(rintf(__ldg(&kp[ 9 + (8 - k)])), -1.0f), 1.0f);
            W[k].z = fminf(fmaxf(rintf(__ldg(&kp[18 + (8 - k)])), -1.0f), 1.0f);
            W[k].w = fminf(fmaxf(rintf(__ldg(&kp[27 + (8 - k)])), -1.0f), 1.0f);
        }
    }
    float4 BIA;
    BIA.x = rintf(__ldg(&bias[4 * q + 0]));
    BIA.y = rintf(__ldg(&bias[4 * q + 1]));
    BIA.z = rintf(__ldg(&bias[4 * q + 2]));
    BIA.w = rintf(__ldg(&bias[4 * q + 3]));

    // ---- div-free vectorized fill: 10 rows x 16 float4 tasks (cols 0..63) ----
    // gc0+63 <= 511 always -> only rows need guards. 160 tasks / 256 threads.
    const float* xb = x + (size_t)b * HW * HW;
    for (int t = tid; t < SM_ROWS * 16; t += 256) {
        int r = t >> 4;
        int k = (t & 15) << 2;
        int gr = gr0 + r;
        float4 v = make_float4(0.f, 0.f, 0.f, 0.f);
        if (gr < HW)
            v = *(const float4*)&xb[gr * HW + gc0 + k];
        v.x = rintf(v.x); v.y = rintf(v.y); v.z = rintf(v.z); v.w = rintf(v.w);
        *(float4*)&sx[r * SM_STRIDE + k] = v;
    }
    // tail: tile cols 64..67 (row+col guarded; 40 threads)
    if (tid < SM_ROWS * 4) {
        int r = tid >> 2;
        int c = 64 + (tid & 3);
        int gr = gr0 + r;
        int gc = gc0 + c;
        float v = 0.0f;
        if (gr < HW && gc < HW) v = rintf(xb[gr * HW + gc]);
        sx[r * SM_STRIDE + c] = v;
    }
    __syncthreads();

    const int i = gr0 + wrp;
    if (i >= OHW) return;

    const int c0 = px * PXT;                   // thread's first local col
    const int gcol = gc0 + c0;                 // global col of pixel j=0 (<= 496)

    const float* r0p = &sx[(wrp + 0) * SM_STRIDE + c0];
    const float* r1p = &sx[(wrp + 1) * SM_STRIDE + c0];
    const float* r2p = &sx[(wrp + 2) * SM_STRIDE + c0];

    // per-thread sliding window: cols c, c+1 held for 3 rows
    float a0 = r0p[0], b0 = r0p[1];
    float a1 = r1p[0], b1 = r1p[1];
    float a2 = r2p[0], b2 = r2p[1];

    // store pointer: element (b, i, gcol, 4q); 16B aligned
    float4* op = (float4*)(out + (((size_t)b * OHW + i) * OHW + gcol) * NF + 4 * q);

    #pragma unroll 4
    for (int j = 0; j < PXT; ++j) {
        float n0 = r0p[j + 2];
        float n1 = r1p[j + 2];
        float n2 = r2p[j + 2];

        float4 acc = BIA;
        acc.x = fmaf(a0, W[0].x, acc.x); acc.y = fmaf(a0, W[0].y, acc.y);
        acc.z = fmaf(a0, W[0].z, acc.z); acc.w = fmaf(a0, W[0].w, acc.w);
        acc.x = fmaf(b0, W[1].x, acc.x); acc.y = fmaf(b0, W[1].y, acc.y);
        acc.z = fmaf(b0, W[1].z, acc.z); acc.w = fmaf(b0, W[1].w, acc.w);
        acc.x = fmaf(n0, W[2].x, acc.x); acc.y = fmaf(n0, W[2].y, acc.y);
        acc.z = fmaf(n0, W[2].z, acc.z); acc.w = fmaf(n0, W[2].w, acc.w);

        acc.x = fmaf(a1, W[3].x, acc.x); acc.y = fmaf(a1, W[3].y, acc.y);
        acc.z = fmaf(a1, W[3].z, acc.z); acc.w = fmaf(a1, W[3].w, acc.w);
        acc.x = fmaf(b1, W[4].x, acc.x); acc.y = fmaf(b1, W[4].y, acc.y);
        acc.z = fmaf(b1, W[4].z, acc.z); acc.w = fmaf(b1, W[4].w, acc.w);
        acc.x = fmaf(n1, W[5].x, acc.x); acc.y = fmaf(n1, W[5].y, acc.y);
        acc.z = fmaf(n1, W[5].z, acc.z); acc.w = fmaf(n1, W[5].w, acc.w);

        acc.x = fmaf(a2, W[6].x, acc.x); acc.y = fmaf(a2, W[6].y, acc.y);
        acc.z = fmaf(a2, W[6].z, acc.z); acc.w = fmaf(a2, W[6].w, acc.w);
        acc.x = fmaf(b2, W[7].x, acc.x); acc.y = fmaf(b2, W[7].y, acc.y);
        acc.z = fmaf(b2, W[7].z, acc.z); acc.w = fmaf(b2, W[7].w, acc.w);
        acc.x = fmaf(n2, W[8].x, acc.x); acc.y = fmaf(n2, W[8].y, acc.y);
        acc.z = fmaf(n2, W[8].z, acc.z); acc.w = fmaf(n2, W[8].w, acc.w);

        acc.x = fmaxf(acc.x, 0.0f);
        acc.y = fmaxf(acc.y, 0.0f);
        acc.z = fmaxf(acc.z, 0.0f);
        acc.w = fmaxf(acc.w, 0.0f);

        // column guard only binds in the last column block (gcol+j can reach 511)
        if (gcol + j < OHW)
            __stcs(op, acc);
        op += NF / 4;                 // next pixel: +32 floats

        a0 = b0; b0 = n0;
        a1 = b1; b1 = n1;
        a2 = b2; b2 = n2;
    }
}

extern "C" void kernel_launch(void* const* d_in, const int* in_sizes, int n_in,
                              void* d_out, int out_size)
{
    const float* x    = (const float*)d_in[0];
    const float* kw   = (const float*)d_in[1];
    const float* bias = (const float*)d_in[2];
    float* out = (float*)d_out;

    dim3 grid((OHW + TC - 1) / TC,   // 8
              (OHW + TR - 1) / TR,   // 64
              BATCH);                // 32 -> 16384 blocks
    cwtconv2d_kernel<<<grid, 256>>>(x, kw, bias, out);
}